// round 1
// baseline (speedup 1.0000x reference)
#include <cuda_runtime.h>
#include <math.h>

#define NATOMS 10000
#define NPAIR  100000
#define FDIM   128
#define NHEAD  4
#define FHD    32
#define NDEG   3
#define MTOT   15
#define KRBF   32

// Scratch (static device allocations — allowed)
__device__ float d_xh[NATOMS * FDIM];                 //  5.1 MB  x@W_in+b
__device__ float d_Q [NATOMS * NDEG * NHEAD * FHD];   // 15.4 MB
__device__ float d_Kb[NATOMS * NDEG * NHEAD * FHD];   // 15.4 MB
__device__ float d_P [NATOMS * NHEAD * FDIM];         // 20.5 MB  per-head W_out projection
__device__ float d_alpha[(size_t)NPAIR * NDEG * NHEAD]; // 4.8 MB

// ---------------------------------------------------------------------------
// Generic C[M,128] = A[M,K] @ B[K,128] (+bias), row-major, BM=128 BN=128 BK=16
// ---------------------------------------------------------------------------
__global__ __launch_bounds__(256) void gemm128(
    const float* __restrict__ A, int lda,
    const float* __restrict__ B, int ldb,
    const float* __restrict__ bias,
    float* __restrict__ C, int ldc,
    int M, int K)
{
    __shared__ float sA[16][132];   // [k][row], padded
    __shared__ float sB[16][128];   // [k][col]
    int tid = threadIdx.x;
    int tx = tid & 15, ty = tid >> 4;
    int r0 = blockIdx.x * 128;

    float acc[8][8];
#pragma unroll
    for (int i = 0; i < 8; i++)
#pragma unroll
        for (int j = 0; j < 8; j++) acc[i][j] = 0.f;

    for (int kk = 0; kk < K; kk += 16) {
        // A tile: 128 rows x 16 k  (512 float4, 2 per thread)
#pragma unroll
        for (int l = 0; l < 2; l++) {
            int p   = tid + l * 256;
            int row = p >> 2;
            int q   = p & 3;
            float4 v = make_float4(0.f, 0.f, 0.f, 0.f);
            if (r0 + row < M)
                v = *(const float4*)(A + (size_t)(r0 + row) * lda + kk + q * 4);
            sA[q*4+0][row] = v.x; sA[q*4+1][row] = v.y;
            sA[q*4+2][row] = v.z; sA[q*4+3][row] = v.w;
        }
        // B tile: 16 k x 128 cols
#pragma unroll
        for (int l = 0; l < 2; l++) {
            int p    = tid + l * 256;
            int krow = p >> 5;
            int c4   = p & 31;
            float4 v = *(const float4*)(B + (size_t)(kk + krow) * ldb + c4 * 4);
            *(float4*)&sB[krow][c4 * 4] = v;
        }
        __syncthreads();
#pragma unroll
        for (int k = 0; k < 16; k++) {
            float ra[8], rb[8];
#pragma unroll
            for (int i = 0; i < 8; i++) ra[i] = sA[k][ty*8 + i];
#pragma unroll
            for (int j = 0; j < 8; j++) rb[j] = sB[k][tx*8 + j];
#pragma unroll
            for (int i = 0; i < 8; i++)
#pragma unroll
                for (int j = 0; j < 8; j++)
                    acc[i][j] += ra[i] * rb[j];
        }
        __syncthreads();
    }

    float bv[8];
#pragma unroll
    for (int j = 0; j < 8; j++) bv[j] = bias ? bias[tx*8 + j] : 0.f;
#pragma unroll
    for (int i = 0; i < 8; i++) {
        int row = r0 + ty*8 + i;
        if (row < M) {
#pragma unroll
            for (int j = 0; j < 8; j++)
                C[(size_t)row * ldc + tx*8 + j] = acc[i][j] + bv[j];
        }
    }
}

// ---------------------------------------------------------------------------
// Q[n,dh,i] = sum_j W_Q[dh,i,j] * xh[n, h*32+j];  same for K.  32 atoms/block.
// ---------------------------------------------------------------------------
__global__ __launch_bounds__(128) void qk_kernel(const float* __restrict__ WQ,
                                                 const float* __restrict__ WK)
{
    __shared__ float sx[32][128];
    __shared__ float sw[2][32][33];     // padded to kill bank conflicts
    int tid = threadIdx.x;
    int a0  = blockIdx.x * 32;
    for (int idx = tid; idx < 32 * 128; idx += 128) {
        int a = idx >> 7, c = idx & 127;
        sx[a][c] = (a0 + a < NATOMS) ? d_xh[(size_t)(a0 + a) * 128 + c] : 0.f;
    }
    int lane  = tid & 31;
    int awarp = tid >> 5;   // 0..3

    for (int dh = 0; dh < 12; dh++) {
        __syncthreads();
        for (int idx = tid; idx < 1024; idx += 128) {
            sw[0][idx >> 5][idx & 31] = WQ[dh * 1024 + idx];
            sw[1][idx >> 5][idx & 31] = WK[dh * 1024 + idx];
        }
        __syncthreads();
        int h = dh & 3;
        float qa[8], ka[8];
#pragma unroll
        for (int r = 0; r < 8; r++) { qa[r] = 0.f; ka[r] = 0.f; }
#pragma unroll
        for (int j = 0; j < 32; j++) {
            float wq = sw[0][lane][j];
            float wk = sw[1][lane][j];
#pragma unroll
            for (int r = 0; r < 8; r++) {
                float xv = sx[awarp + r*4][h*32 + j];
                qa[r] += wq * xv;
                ka[r] += wk * xv;
            }
        }
#pragma unroll
        for (int r = 0; r < 8; r++) {
            int a = awarp + r*4;
            if (a0 + a < NATOMS) {
                d_Q [(size_t)(a0 + a) * 384 + dh*32 + lane] = qa[r];
                d_Kb[(size_t)(a0 + a) * 384 + dh*32 + lane] = ka[r];
            }
        }
    }
}

// ---------------------------------------------------------------------------
// Per-pair: h1 = ssp(rbf@Wf1+bf1); Wij = h1@Wf2+bf2;
// alpha[dh] = phi*mask^3/sqrt(32) * sum_f Q_i*K_j*Wij.
// Warp handles 4 pairs at once (register-blocks the 32x384 contraction).
// Wf2 in smem relaid as [k][lane][dh] so each lane reads 3x LDS.128.
// ---------------------------------------------------------------------------
__global__ __launch_bounds__(256) void alpha_kernel(
    const float* __restrict__ rbf,  const float* __restrict__ phi,
    const float* __restrict__ pmask,
    const int*   __restrict__ idx_i, const int* __restrict__ idx_j,
    const float* __restrict__ Wf1,  const float* __restrict__ bf1,
    const float* __restrict__ Wf2,  const float* __restrict__ bf2)
{
    __shared__ __align__(16) float sW[KRBF * 384];   // 48 KB
    int tid = threadIdx.x;
    for (int idx = tid; idx < KRBF * 384; idx += 256) {
        int k = idx / 384, f = idx - k * 384;
        sW[k * 384 + (f & 31) * 12 + (f >> 5)] = Wf2[idx];
    }
    int lane = tid & 31;
    float wf1[32];
#pragma unroll
    for (int r = 0; r < 32; r++) wf1[r] = Wf1[r * 32 + lane];
    float bf1v = bf1[lane];
    float bf2v[12];
#pragma unroll
    for (int d = 0; d < 12; d++) bf2v[d] = bf2[d * 32 + lane];
    __syncthreads();

    int warp  = blockIdx.x * 8 + (tid >> 5);
    int nwarp = gridDim.x * 8;

    for (int pb = warp * 4; pb < NPAIR; pb += nwarp * 4) {
        // ---- h1 for 4 pairs (lane k owns h1[k]) ----
        float h1[4];
#pragma unroll
        for (int q = 0; q < 4; q++) {
            float rv = rbf[(size_t)(pb + q) * 32 + lane];
            float t = bf1v;
#pragma unroll
            for (int r = 0; r < 32; r++)
                t += __shfl_sync(0xffffffffu, rv, r) * wf1[r];
            float sp = (t > 20.f) ? t : log1pf(expf(t));
            h1[q] = sp - 0.69314718055994531f;
        }
        // ---- Wij accumulation: wacc[q][dh] at f = dh*32+lane ----
        float wacc[4][12];
#pragma unroll
        for (int q = 0; q < 4; q++)
#pragma unroll
            for (int d = 0; d < 12; d++) wacc[q][d] = bf2v[d];

#pragma unroll 4
        for (int k = 0; k < 32; k++) {
            const float4* wp = (const float4*)&sW[k * 384 + lane * 12];
            float4 w0 = wp[0], w1 = wp[1], w2 = wp[2];
#pragma unroll
            for (int q = 0; q < 4; q++) {
                float hk = __shfl_sync(0xffffffffu, h1[q], k);
                wacc[q][0]  += hk * w0.x; wacc[q][1]  += hk * w0.y;
                wacc[q][2]  += hk * w0.z; wacc[q][3]  += hk * w0.w;
                wacc[q][4]  += hk * w1.x; wacc[q][5]  += hk * w1.y;
                wacc[q][6]  += hk * w1.z; wacc[q][7]  += hk * w1.w;
                wacc[q][8]  += hk * w2.x; wacc[q][9]  += hk * w2.y;
                wacc[q][10] += hk * w2.z; wacc[q][11] += hk * w2.w;
            }
        }
        // ---- alpha = reduce_f Q*K*Wij, scaled ----
#pragma unroll
        for (int q = 0; q < 4; q++) {
            int p  = pb + q;
            int ii = idx_i[p], jj = idx_j[p];
            const float* Qr = &d_Q [(size_t)ii * 384 + lane];
            const float* Kr = &d_Kb[(size_t)jj * 384 + lane];
            float m = pmask[p];
            float scale = phi[p] * m * m * m * 0.17677669529663687f;
            float my = 0.f;
#pragma unroll
            for (int d = 0; d < 12; d++) {
                float partial = Qr[d * 32] * Kr[d * 32] * wacc[q][d];
#pragma unroll
                for (int o = 16; o > 0; o >>= 1)
                    partial += __shfl_xor_sync(0xffffffffu, partial, o);
                if (lane == d) my = partial * scale;
            }
            if (lane < 12) d_alpha[(size_t)p * 12 + lane] = my;
        }
    }
}

// ---------------------------------------------------------------------------
// Per-atom-i aggregation, writes the FINAL output directly:
// out[i,m,c] = b_out[c] + sum_p sph[p,m] * sum_h alpha[p,deg(m)*4+h]*P[j,h,c]
// idx_i is sorted -> binary search segment bounds. One block per atom.
// ---------------------------------------------------------------------------
__global__ __launch_bounds__(128) void agg_kernel(
    const int*   __restrict__ idx_i, const int* __restrict__ idx_j,
    const float* __restrict__ sph,   const float* __restrict__ b_out,
    float* __restrict__ out)
{
    int atom = blockIdx.x;
    int c    = threadIdx.x;   // 0..127
    __shared__ int   srange[2];
    __shared__ int   sj;
    __shared__ float sal[12];
    __shared__ float s_sph[15];

    if (c < 2) {
        int target = atom + c;
        int lo = 0, hi = NPAIR;
        while (lo < hi) {
            int mid = (lo + hi) >> 1;
            if (idx_i[mid] < target) lo = mid + 1; else hi = mid;
        }
        srange[c] = lo;
    }
    __syncthreads();
    int p0 = srange[0], p1 = srange[1];

    float acc[15];
#pragma unroll
    for (int m = 0; m < 15; m++) acc[m] = 0.f;

    for (int p = p0; p < p1; p++) {
        if (c < 12)                 sal[c]       = d_alpha[(size_t)p * 12 + c];
        else if (c == 16)           sj           = idx_j[p];
        else if (c >= 32 && c < 47) s_sph[c-32]  = sph[(size_t)p * 15 + (c - 32)];
        __syncthreads();
        int j = sj;
        const float* Pr = &d_P[(size_t)j * 512 + c];
        float pv0 = Pr[0], pv1 = Pr[128], pv2 = Pr[256], pv3 = Pr[384];
        float e0 = sal[0]*pv0 + sal[1]*pv1 + sal[2]*pv2  + sal[3]*pv3;
        float e1 = sal[4]*pv0 + sal[5]*pv1 + sal[6]*pv2  + sal[7]*pv3;
        float e2 = sal[8]*pv0 + sal[9]*pv1 + sal[10]*pv2 + sal[11]*pv3;
        acc[0]  += s_sph[0]  * e0;
        acc[1]  += s_sph[1]  * e0;
        acc[2]  += s_sph[2]  * e0;
        acc[3]  += s_sph[3]  * e1;
        acc[4]  += s_sph[4]  * e1;
        acc[5]  += s_sph[5]  * e1;
        acc[6]  += s_sph[6]  * e1;
        acc[7]  += s_sph[7]  * e1;
        acc[8]  += s_sph[8]  * e2;
        acc[9]  += s_sph[9]  * e2;
        acc[10] += s_sph[10] * e2;
        acc[11] += s_sph[11] * e2;
        acc[12] += s_sph[12] * e2;
        acc[13] += s_sph[13] * e2;
        acc[14] += s_sph[14] * e2;
        __syncthreads();
    }

    float bo = b_out[c];
#pragma unroll
    for (int m = 0; m < 15; m++)
        out[((size_t)atom * 15 + m) * 128 + c] = acc[m] + bo;
}

// ---------------------------------------------------------------------------
extern "C" void kernel_launch(void* const* d_in, const int* in_sizes, int n_in,
                              void* d_out, int out_size)
{
    const float* x     = (const float*)d_in[0];
    const float* rbf   = (const float*)d_in[1];
    const float* sph   = (const float*)d_in[2];
    const float* phi   = (const float*)d_in[3];
    const int*   idx_i = (const int*)  d_in[4];
    const int*   idx_j = (const int*)  d_in[5];
    const float* pmask = (const float*)d_in[6];
    const float* WQ    = (const float*)d_in[7];
    const float* WK    = (const float*)d_in[8];
    const float* W_in  = (const float*)d_in[9];
    const float* b_in  = (const float*)d_in[10];
    const float* Wf1   = (const float*)d_in[11];
    const float* bf1   = (const float*)d_in[12];
    const float* Wf2   = (const float*)d_in[13];
    const float* bf2   = (const float*)d_in[14];
    const float* W_out = (const float*)d_in[15];
    const float* b_out = (const float*)d_in[16];
    float* out = (float*)d_out;

    float *xh = nullptr, *P = nullptr;
    cudaGetSymbolAddress((void**)&xh, d_xh);
    cudaGetSymbolAddress((void**)&P,  d_P);

    // 1) xh = x @ W_in + b_in
    gemm128<<<(NATOMS + 127) / 128, 256>>>(x, 128, W_in, 128, b_in, xh, 128,
                                           NATOMS, 128);
    // 2) Q, K per atom
    qk_kernel<<<(NATOMS + 31) / 32, 128>>>(WQ, WK);
    // 3) P[j,h,:] = x_head[j,h,:] @ W_out[h*32:(h+1)*32, :]   (4 thin GEMMs)
    for (int h = 0; h < 4; h++)
        gemm128<<<(NATOMS + 127) / 128, 256>>>(xh + h * 32, 128,
                                               W_out + h * 32 * 128, 128,
                                               nullptr, P + h * 128, 512,
                                               NATOMS, 32);
    // 4) per-pair attention coefficients
    alpha_kernel<<<444, 256>>>(rbf, phi, pmask, idx_i, idx_j, Wf1, bf1, Wf2, bf2);
    // 5) segment aggregation + fused output projection (writes d_out)
    agg_kernel<<<NATOMS, 128>>>(idx_i, idx_j, sph, b_out, out);
}

// round 2
// speedup vs baseline: 1.5856x; 1.5856x over previous
#include <cuda_runtime.h>
#include <math.h>

#define NATOMS 10000
#define NPAIR  100000

// Scratch (static device allocations — allowed)
__device__ float d_Q [NATOMS * 384];             // [atom][dh*32+i], dh = d*4+h
__device__ float d_Kb[NATOMS * 384];
__device__ float d_P [NATOMS * 512];             // [atom][h*128+c]  (xh_head @ W_out block)
__device__ float d_alpha[(size_t)NPAIR * 12];    // [pair][d*4+h]

// ---------------------------------------------------------------------------
// Fused per-atom prep: xh = x@W_in + b (kept in smem only), then
// Q/K (12 block-diagonal 32x32 gemms) and P (4 head projections 32x128).
// 32 atoms per block, 256 threads. Grid 313.
// ---------------------------------------------------------------------------
__global__ __launch_bounds__(256) void prep_kernel(
    const float* __restrict__ x,    const float* __restrict__ W_in,
    const float* __restrict__ b_in,
    const float* __restrict__ WQ,   const float* __restrict__ WK,
    const float* __restrict__ W_out)
{
    __shared__ float sx[32][128];          // x tile, then xh tile
    union UB { float w[32][128]; float qk[2][32][33]; };
    __shared__ UB sb;

    int tid  = threadIdx.x;
    int wid  = tid >> 5, lane = tid & 31;
    int a0   = blockIdx.x * 32;

    // load x tile (1024 float4, 4 per thread), zero-pad past NATOMS
#pragma unroll
    for (int t = 0; t < 4; t++) {
        int p = tid + t * 256;
        int row = p >> 5, c4 = p & 31;
        float4 v = make_float4(0.f, 0.f, 0.f, 0.f);
        if (a0 + row < NATOMS)
            v = *(const float4*)(x + (size_t)(a0 + row) * 128 + c4 * 4);
        *(float4*)&sx[row][c4 * 4] = v;
    }

    // ---- xh = x @ W_in : micro 4 rows (wid*4..) x 4 cols (lane*4..) ----
    float acc[4][4];
#pragma unroll
    for (int i = 0; i < 4; i++)
#pragma unroll
        for (int j = 0; j < 4; j++) acc[i][j] = 0.f;

    for (int kk = 0; kk < 128; kk += 32) {
        __syncthreads();
#pragma unroll
        for (int t = 0; t < 4; t++) {
            int p = tid + t * 256;
            int kr = p >> 5, c4 = p & 31;
            *(float4*)&sb.w[kr][c4 * 4] =
                *(const float4*)(W_in + (size_t)(kk + kr) * 128 + c4 * 4);
        }
        __syncthreads();
#pragma unroll
        for (int k = 0; k < 32; k++) {
            float4 b = *(float4*)&sb.w[k][lane * 4];
#pragma unroll
            for (int i = 0; i < 4; i++) {
                float a = sx[wid * 4 + i][kk + k];
                acc[i][0] += a * b.x; acc[i][1] += a * b.y;
                acc[i][2] += a * b.z; acc[i][3] += a * b.w;
            }
        }
    }
    __syncthreads();
    {   // overwrite sx with xh (+bias)
        float4 bb = *(const float4*)(b_in + lane * 4);
#pragma unroll
        for (int i = 0; i < 4; i++) {
            float4 v = make_float4(acc[i][0] + bb.x, acc[i][1] + bb.y,
                                   acc[i][2] + bb.z, acc[i][3] + bb.w);
            *(float4*)&sx[wid * 4 + i][lane * 4] = v;
        }
    }

    // ---- Q, K : 12 x (32x32) block-diagonal ----
    for (int dh = 0; dh < 12; dh++) {
        __syncthreads();
        for (int t = tid; t < 1024; t += 256) {
            sb.qk[0][t >> 5][t & 31] = WQ[dh * 1024 + t];
            sb.qk[1][t >> 5][t & 31] = WK[dh * 1024 + t];
        }
        __syncthreads();
        int h = dh & 3;
        float qa[4] = {0.f, 0.f, 0.f, 0.f};
        float ka[4] = {0.f, 0.f, 0.f, 0.f};
#pragma unroll
        for (int j = 0; j < 32; j++) {
            float wq = sb.qk[0][lane][j];
            float wk = sb.qk[1][lane][j];
#pragma unroll
            for (int r = 0; r < 4; r++) {
                float xv = sx[wid * 4 + r][h * 32 + j];
                qa[r] += wq * xv;
                ka[r] += wk * xv;
            }
        }
#pragma unroll
        for (int r = 0; r < 4; r++) {
            int a = a0 + wid * 4 + r;
            if (a < NATOMS) {
                d_Q [(size_t)a * 384 + dh * 32 + lane] = qa[r];
                d_Kb[(size_t)a * 384 + dh * 32 + lane] = ka[r];
            }
        }
    }

    // ---- P[a][h*128+c] = xh_head[a,h,:] @ W_out[h*32:(h+1)*32, :] ----
    for (int h = 0; h < 4; h++) {
        __syncthreads();
#pragma unroll
        for (int t = 0; t < 4; t++) {
            int p = tid + t * 256;
            int kr = p >> 5, c4 = p & 31;
            *(float4*)&sb.w[kr][c4 * 4] =
                *(const float4*)(W_out + (size_t)(h * 32 + kr) * 128 + c4 * 4);
        }
        __syncthreads();
        float pa[4][4];
#pragma unroll
        for (int i = 0; i < 4; i++)
#pragma unroll
            for (int j = 0; j < 4; j++) pa[i][j] = 0.f;
#pragma unroll
        for (int k = 0; k < 32; k++) {
            float4 b = *(float4*)&sb.w[k][lane * 4];
#pragma unroll
            for (int i = 0; i < 4; i++) {
                float a = sx[wid * 4 + i][h * 32 + k];
                pa[i][0] += a * b.x; pa[i][1] += a * b.y;
                pa[i][2] += a * b.z; pa[i][3] += a * b.w;
            }
        }
#pragma unroll
        for (int i = 0; i < 4; i++) {
            int a = a0 + wid * 4 + i;
            if (a < NATOMS) {
                float4 v = make_float4(pa[i][0], pa[i][1], pa[i][2], pa[i][3]);
                *(float4*)&d_P[(size_t)a * 512 + h * 128 + lane * 4] = v;
            }
        }
    }
}

// ---------------------------------------------------------------------------
// Per-pair: h1 = ssp(rbf@Wf1+bf1); Wij = h1@Wf2+bf2;
// alpha[dh] = phi*mask^3/sqrt(32) * sum_f Q_i*K_j*Wij.
// Warp handles 4 pairs; Wf2 relaid [k][lane][12] (verified conflict-free for
// the 3x LDS.128). Wf1 in smem to keep regs <=128 (2 blocks/SM).
// ---------------------------------------------------------------------------
__global__ __launch_bounds__(256, 2) void alpha_kernel(
    const float* __restrict__ rbf,  const float* __restrict__ phi,
    const float* __restrict__ pmask,
    const int*   __restrict__ idx_i, const int* __restrict__ idx_j,
    const float* __restrict__ Wf1,  const float* __restrict__ bf1,
    const float* __restrict__ Wf2,  const float* __restrict__ bf2)
{
    __shared__ __align__(16) float sW[32 * 384];   // 48 KB
    __shared__ float sWf1[32][33];
    int tid = threadIdx.x;
    for (int idx = tid; idx < 32 * 384; idx += 256) {
        int k = idx / 384, f = idx - k * 384;
        sW[k * 384 + (f & 31) * 12 + (f >> 5)] = Wf2[idx];
    }
    for (int t = tid; t < 1024; t += 256) sWf1[t >> 5][t & 31] = Wf1[t];
    int lane = tid & 31;
    float bf1v = bf1[lane];
    float bf2v[12];
#pragma unroll
    for (int d = 0; d < 12; d++) bf2v[d] = bf2[d * 32 + lane];
    __syncthreads();

    int warp  = blockIdx.x * 8 + (tid >> 5);
    int nwarp = gridDim.x * 8;

    for (int pb = warp * 4; pb < NPAIR; pb += nwarp * 4) {
        // ---- h1 for 4 pairs (lane k owns h1[k]) ----
        float h1[4];
#pragma unroll
        for (int q = 0; q < 4; q++) {
            float rv = rbf[(size_t)(pb + q) * 32 + lane];
            float t = bf1v;
#pragma unroll
            for (int r = 0; r < 32; r++)
                t += __shfl_sync(0xffffffffu, rv, r) * sWf1[r][lane];
            float sp = (t > 20.f) ? t : log1pf(expf(t));
            h1[q] = sp - 0.69314718055994531f;
        }
        // ---- Wij accumulation: wacc[q][dh] at f = dh*32+lane ----
        float wacc[4][12];
#pragma unroll
        for (int q = 0; q < 4; q++)
#pragma unroll
            for (int d = 0; d < 12; d++) wacc[q][d] = bf2v[d];

#pragma unroll 4
        for (int k = 0; k < 32; k++) {
            const float4* wp = (const float4*)&sW[k * 384 + lane * 12];
            float4 w0 = wp[0], w1 = wp[1], w2 = wp[2];
#pragma unroll
            for (int q = 0; q < 4; q++) {
                float hk = __shfl_sync(0xffffffffu, h1[q], k);
                wacc[q][0]  += hk * w0.x; wacc[q][1]  += hk * w0.y;
                wacc[q][2]  += hk * w0.z; wacc[q][3]  += hk * w0.w;
                wacc[q][4]  += hk * w1.x; wacc[q][5]  += hk * w1.y;
                wacc[q][6]  += hk * w1.z; wacc[q][7]  += hk * w1.w;
                wacc[q][8]  += hk * w2.x; wacc[q][9]  += hk * w2.y;
                wacc[q][10] += hk * w2.z; wacc[q][11] += hk * w2.w;
            }
        }
        // ---- alpha = reduce_f Q*K*Wij, scaled ----
#pragma unroll
        for (int q = 0; q < 4; q++) {
            int p  = pb + q;
            int ii = idx_i[p], jj = idx_j[p];
            const float* Qr = &d_Q [(size_t)ii * 384 + lane];
            const float* Kr = &d_Kb[(size_t)jj * 384 + lane];
            float m = pmask[p];
            float scale = phi[p] * m * m * m * 0.17677669529663687f;
            float my = 0.f;
#pragma unroll
            for (int d = 0; d < 12; d++) {
                float partial = Qr[d * 32] * Kr[d * 32] * wacc[q][d];
#pragma unroll
                for (int o = 16; o > 0; o >>= 1)
                    partial += __shfl_xor_sync(0xffffffffu, partial, o);
                if (lane == d) my = partial * scale;
            }
            if (lane < 12) d_alpha[(size_t)p * 12 + lane] = my;
        }
    }
}

// ---------------------------------------------------------------------------
// Per-atom-i aggregation, double-buffered prefetch, one sync per pair.
// out[i,m,c] = b_out[c] + sum_p sph[p,m] * sum_h alpha[p,deg(m)*4+h]*P[j,h,c]
// ---------------------------------------------------------------------------
__global__ __launch_bounds__(128) void agg_kernel(
    const int*   __restrict__ idx_i, const int* __restrict__ idx_j,
    const float* __restrict__ sph,   const float* __restrict__ b_out,
    float* __restrict__ out)
{
    int atom = blockIdx.x;
    int c    = threadIdx.x;   // 0..127
    __shared__ int   srange[2];
    __shared__ int   sj[2];
    __shared__ float sal[2][12];
    __shared__ float ssph[2][16];

    if (c < 2) {
        int target = atom + c;
        int lo = 0, hi = NPAIR;
        while (lo < hi) {
            int mid = (lo + hi) >> 1;
            if (idx_i[mid] < target) lo = mid + 1; else hi = mid;
        }
        srange[c] = lo;
    }
    __syncthreads();
    int p0 = srange[0], p1 = srange[1];

    float acc[15];
#pragma unroll
    for (int m = 0; m < 15; m++) acc[m] = 0.f;

    if (p0 < p1) {
        if (c < 12)                 sal[0][c]      = d_alpha[(size_t)p0 * 12 + c];
        else if (c == 12)           sj[0]          = idx_j[p0];
        else if (c >= 32 && c < 47) ssph[0][c-32]  = sph[(size_t)p0 * 15 + (c - 32)];
    }
    __syncthreads();

    for (int p = p0; p < p1; p++) {
        int b  = (p - p0) & 1;
        int nb = b ^ 1;
        if (p + 1 < p1) {   // prefetch next pair while computing current
            if (c < 12)                 sal[nb][c]      = d_alpha[(size_t)(p+1) * 12 + c];
            else if (c == 12)           sj[nb]          = idx_j[p+1];
            else if (c >= 32 && c < 47) ssph[nb][c-32]  = sph[(size_t)(p+1) * 15 + (c - 32)];
        }
        int j = sj[b];
        const float* Pr = &d_P[(size_t)j * 512 + c];
        float pv0 = Pr[0], pv1 = Pr[128], pv2 = Pr[256], pv3 = Pr[384];
        float e0 = sal[b][0]*pv0 + sal[b][1]*pv1 + sal[b][2] *pv2 + sal[b][3] *pv3;
        float e1 = sal[b][4]*pv0 + sal[b][5]*pv1 + sal[b][6] *pv2 + sal[b][7] *pv3;
        float e2 = sal[b][8]*pv0 + sal[b][9]*pv1 + sal[b][10]*pv2 + sal[b][11]*pv3;
        acc[0]  += ssph[b][0]  * e0;
        acc[1]  += ssph[b][1]  * e0;
        acc[2]  += ssph[b][2]  * e0;
        acc[3]  += ssph[b][3]  * e1;
        acc[4]  += ssph[b][4]  * e1;
        acc[5]  += ssph[b][5]  * e1;
        acc[6]  += ssph[b][6]  * e1;
        acc[7]  += ssph[b][7]  * e1;
        acc[8]  += ssph[b][8]  * e2;
        acc[9]  += ssph[b][9]  * e2;
        acc[10] += ssph[b][10] * e2;
        acc[11] += ssph[b][11] * e2;
        acc[12] += ssph[b][12] * e2;
        acc[13] += ssph[b][13] * e2;
        acc[14] += ssph[b][14] * e2;
        __syncthreads();
    }

    float bo = b_out[c];
#pragma unroll
    for (int m = 0; m < 15; m++)
        out[((size_t)atom * 15 + m) * 128 + c] = acc[m] + bo;
}

// ---------------------------------------------------------------------------
extern "C" void kernel_launch(void* const* d_in, const int* in_sizes, int n_in,
                              void* d_out, int out_size)
{
    const float* x     = (const float*)d_in[0];
    const float* rbf   = (const float*)d_in[1];
    const float* sph   = (const float*)d_in[2];
    const float* phi   = (const float*)d_in[3];
    const int*   idx_i = (const int*)  d_in[4];
    const int*   idx_j = (const int*)  d_in[5];
    const float* pmask = (const float*)d_in[6];
    const float* WQ    = (const float*)d_in[7];
    const float* WK    = (const float*)d_in[8];
    const float* W_in  = (const float*)d_in[9];
    const float* b_in  = (const float*)d_in[10];
    const float* Wf1   = (const float*)d_in[11];
    const float* bf1   = (const float*)d_in[12];
    const float* Wf2   = (const float*)d_in[13];
    const float* bf2   = (const float*)d_in[14];
    const float* W_out = (const float*)d_in[15];
    const float* b_out = (const float*)d_in[16];
    float* out = (float*)d_out;

    // 1) fused xh + Q/K + P (xh never leaves shared memory)
    prep_kernel<<<(NATOMS + 31) / 32, 256>>>(x, W_in, b_in, WQ, WK, W_out);
    // 2) per-pair attention coefficients
    alpha_kernel<<<296, 256>>>(rbf, phi, pmask, idx_i, idx_j, Wf1, bf1, Wf2, bf2);
    // 3) segment aggregation + fused output projection (writes d_out)
    agg_kernel<<<NATOMS, 128>>>(idx_i, idx_j, sph, b_out, out);
}

// round 3
// speedup vs baseline: 1.7065x; 1.0762x over previous
#include <cuda_runtime.h>
#include <math.h>

#define NATOMS 10000
#define NPAIR  100000

// Scratch (static device allocations — allowed)
__device__ float d_Q [NATOMS * 384];             // [atom][dh*32+i], dh = d*4+h
__device__ float d_Kb[NATOMS * 384];
__device__ float d_P [NATOMS * 512];             // [atom][h*128+c]
__device__ float d_alpha[(size_t)NPAIR * 12];    // [pair][d*4+h]

// ---------------------------------------------------------------------------
// Fused per-atom prep with register-pipelined weight streaming.
// 32 atoms / 256 threads per block. xh lives only in smem.
// ---------------------------------------------------------------------------
__global__ __launch_bounds__(256) void prep_kernel(
    const float* __restrict__ x,    const float* __restrict__ W_in,
    const float* __restrict__ b_in,
    const float* __restrict__ WQ,   const float* __restrict__ WK,
    const float* __restrict__ W_out)
{
    __shared__ float sx[32][128];              // x tile -> xh tile
    union UB {
        float w[32][128];                      // generic 32x128 weight tile
        float qk[2][2][32][33];                // [Q/K][dh parity][i][j] padded
    };
    __shared__ UB sb;

    int tid  = threadIdx.x;
    int wid  = tid >> 5, lane = tid & 31;
    int a0   = blockIdx.x * 32;

    // ---- load x tile ----
#pragma unroll
    for (int t = 0; t < 4; t++) {
        int p = tid + t * 256;
        int row = p >> 5, c4 = p & 31;
        float4 v = make_float4(0.f, 0.f, 0.f, 0.f);
        if (a0 + row < NATOMS)
            v = *(const float4*)(x + (size_t)(a0 + row) * 128 + c4 * 4);
        *(float4*)&sx[row][c4 * 4] = v;
    }

    // ---- Phase 1: xh = x @ W_in + b  (pipelined W_in tiles) ----
    float4 wr[4];
#pragma unroll
    for (int t = 0; t < 4; t++) {
        int p = tid + t * 256;
        wr[t] = *(const float4*)(W_in + (size_t)(p >> 5) * 128 + (p & 31) * 4);
    }
    float acc[4][4];
#pragma unroll
    for (int i = 0; i < 4; i++)
#pragma unroll
        for (int j = 0; j < 4; j++) acc[i][j] = 0.f;

    for (int kk = 0; kk < 128; kk += 32) {
        __syncthreads();
#pragma unroll
        for (int t = 0; t < 4; t++) {
            int p = tid + t * 256;
            *(float4*)&sb.w[p >> 5][(p & 31) * 4] = wr[t];
        }
        __syncthreads();
        if (kk < 96) {
#pragma unroll
            for (int t = 0; t < 4; t++) {
                int p = tid + t * 256;
                wr[t] = *(const float4*)(W_in + (size_t)(kk + 32 + (p >> 5)) * 128
                                         + (p & 31) * 4);
            }
        }
#pragma unroll
        for (int k = 0; k < 32; k++) {
            float4 b = *(float4*)&sb.w[k][lane * 4];
#pragma unroll
            for (int i = 0; i < 4; i++) {
                float a = sx[wid * 4 + i][kk + k];
                acc[i][0] += a * b.x; acc[i][1] += a * b.y;
                acc[i][2] += a * b.z; acc[i][3] += a * b.w;
            }
        }
    }
    __syncwarp();   // warp owns rows wid*4..+3: ensure reads done before overwrite
    {
        float4 bb = *(const float4*)(b_in + lane * 4);
#pragma unroll
        for (int i = 0; i < 4; i++) {
            float4 v = make_float4(acc[i][0] + bb.x, acc[i][1] + bb.y,
                                   acc[i][2] + bb.z, acc[i][3] + bb.w);
            *(float4*)&sx[wid * 4 + i][lane * 4] = v;
        }
    }
    __syncwarp();

    // ---- Phase 2: Q,K — 6 rounds of 2 dh, pipelined weights ----
    // per round: 4096 floats (2dh x (WQ+WK) x 1024) = 16 floats/thread
    float4 qr[4];
#pragma unroll
    for (int t = 0; t < 4; t++) {
        int e = (tid + t * 256) * 4;
        const float* src = (e >> 11) ? WK : WQ;
        int rem = e & 2047;
        qr[t] = *(const float4*)(src + (rem >> 10) * 1024 + (rem & 1023));
    }
    for (int r = 0; r < 6; r++) {
        __syncthreads();
#pragma unroll
        for (int t = 0; t < 4; t++) {
            int e = (tid + t * 256) * 4;
            int sel = e >> 11, rem = e & 2047;
            int dhp = rem >> 10, w = rem & 1023;
            int i = w >> 5, j = w & 31;
            sb.qk[sel][dhp][i][j + 0] = qr[t].x;
            sb.qk[sel][dhp][i][j + 1] = qr[t].y;
            sb.qk[sel][dhp][i][j + 2] = qr[t].z;
            sb.qk[sel][dhp][i][j + 3] = qr[t].w;
        }
        __syncthreads();
        if (r < 5) {
#pragma unroll
            for (int t = 0; t < 4; t++) {
                int e = (tid + t * 256) * 4;
                const float* src = (e >> 11) ? WK : WQ;
                int rem = e & 2047;
                qr[t] = *(const float4*)(src + (size_t)(2 * (r + 1) + (rem >> 10)) * 1024
                                         + (rem & 1023));
            }
        }
#pragma unroll
        for (int u = 0; u < 2; u++) {
            int dh = 2 * r + u, h = dh & 3;
            float qa[4] = {0.f, 0.f, 0.f, 0.f};
            float ka[4] = {0.f, 0.f, 0.f, 0.f};
#pragma unroll
            for (int j = 0; j < 32; j++) {
                float wq = sb.qk[0][u][lane][j];
                float wk = sb.qk[1][u][lane][j];
#pragma unroll
                for (int rr = 0; rr < 4; rr++) {
                    float xv = sx[wid * 4 + rr][h * 32 + j];
                    qa[rr] += wq * xv;
                    ka[rr] += wk * xv;
                }
            }
#pragma unroll
            for (int rr = 0; rr < 4; rr++) {
                int a = a0 + wid * 4 + rr;
                if (a < NATOMS) {
                    d_Q [(size_t)a * 384 + dh * 32 + lane] = qa[rr];
                    d_Kb[(size_t)a * 384 + dh * 32 + lane] = ka[rr];
                }
            }
        }
    }

    // ---- Phase 3: P — 4 rounds (one per head), pipelined W_out ----
    float4 pr[4];
#pragma unroll
    for (int t = 0; t < 4; t++) {
        int p = tid + t * 256;
        pr[t] = *(const float4*)(W_out + (size_t)(p >> 5) * 128 + (p & 31) * 4);
    }
    for (int h = 0; h < 4; h++) {
        __syncthreads();
#pragma unroll
        for (int t = 0; t < 4; t++) {
            int p = tid + t * 256;
            *(float4*)&sb.w[p >> 5][(p & 31) * 4] = pr[t];
        }
        __syncthreads();
        if (h < 3) {
#pragma unroll
            for (int t = 0; t < 4; t++) {
                int p = tid + t * 256;
                pr[t] = *(const float4*)(W_out + (size_t)((h + 1) * 32 + (p >> 5)) * 128
                                         + (p & 31) * 4);
            }
        }
        float pa[4][4];
#pragma unroll
        for (int i = 0; i < 4; i++)
#pragma unroll
            for (int j = 0; j < 4; j++) pa[i][j] = 0.f;
#pragma unroll
        for (int k = 0; k < 32; k++) {
            float4 b = *(float4*)&sb.w[k][lane * 4];
#pragma unroll
            for (int i = 0; i < 4; i++) {
                float a = sx[wid * 4 + i][h * 32 + k];
                pa[i][0] += a * b.x; pa[i][1] += a * b.y;
                pa[i][2] += a * b.z; pa[i][3] += a * b.w;
            }
        }
#pragma unroll
        for (int i = 0; i < 4; i++) {
            int a = a0 + wid * 4 + i;
            if (a < NATOMS) {
                float4 v = make_float4(pa[i][0], pa[i][1], pa[i][2], pa[i][3]);
                *(float4*)&d_P[(size_t)a * 512 + h * 128 + lane * 4] = v;
            }
        }
    }
}

// ---------------------------------------------------------------------------
// alpha: e = Q_i*K_j preloaded into regs BEFORE the 1536-FFMA wacc loop
// (hides the 24 gather-LDGs per pair). Warp handles 4 pairs.
// ---------------------------------------------------------------------------
__global__ __launch_bounds__(256, 2) void alpha_kernel(
    const float* __restrict__ rbf,  const float* __restrict__ phi,
    const float* __restrict__ pmask,
    const int*   __restrict__ idx_i, const int* __restrict__ idx_j,
    const float* __restrict__ Wf1,  const float* __restrict__ bf1,
    const float* __restrict__ Wf2,  const float* __restrict__ bf2)
{
    __shared__ __align__(16) float sW[32 * 384];   // 48 KB, [k][lane][12]
    __shared__ float sWf1[32][33];
    int tid = threadIdx.x;
    for (int idx = tid; idx < 32 * 384; idx += 256) {
        int k = idx / 384, f = idx - k * 384;
        sW[k * 384 + (f & 31) * 12 + (f >> 5)] = Wf2[idx];
    }
    for (int t = tid; t < 1024; t += 256) sWf1[t >> 5][t & 31] = Wf1[t];
    int lane = tid & 31;
    float bf1v = bf1[lane];
    float bf2v[12];
#pragma unroll
    for (int d = 0; d < 12; d++) bf2v[d] = bf2[d * 32 + lane];
    __syncthreads();

    int warp  = blockIdx.x * 8 + (tid >> 5);
    int nwarp = gridDim.x * 8;

    for (int pb = warp * 4; pb < NPAIR; pb += nwarp * 4) {
        // ---- hoisted gathers: e[q][d] = Q_i * K_j (issued up front) ----
        float e[4][12], scale[4];
#pragma unroll
        for (int q = 0; q < 4; q++) {
            int p  = pb + q;
            int ii = idx_i[p], jj = idx_j[p];
            const float* Qr = &d_Q [(size_t)ii * 384 + lane];
            const float* Kr = &d_Kb[(size_t)jj * 384 + lane];
#pragma unroll
            for (int d = 0; d < 12; d++)
                e[q][d] = Qr[d * 32] * Kr[d * 32];
            float m = pmask[p];
            scale[q] = phi[p] * m * m * m * 0.17677669529663687f;
        }
        // ---- h1 for 4 pairs (lane k owns h1[k]) ----
        float h1[4];
#pragma unroll
        for (int q = 0; q < 4; q++) {
            float rv = rbf[(size_t)(pb + q) * 32 + lane];
            float t = bf1v;
#pragma unroll
            for (int r = 0; r < 32; r++)
                t += __shfl_sync(0xffffffffu, rv, r) * sWf1[r][lane];
            float sp = (t > 20.f) ? t : log1pf(expf(t));
            h1[q] = sp - 0.69314718055994531f;
        }
        // ---- Wij accumulation ----
        float wacc[4][12];
#pragma unroll
        for (int q = 0; q < 4; q++)
#pragma unroll
            for (int d = 0; d < 12; d++) wacc[q][d] = bf2v[d];

#pragma unroll 4
        for (int k = 0; k < 32; k++) {
            const float4* wp = (const float4*)&sW[k * 384 + lane * 12];
            float4 w0 = wp[0], w1 = wp[1], w2 = wp[2];
#pragma unroll
            for (int q = 0; q < 4; q++) {
                float hk = __shfl_sync(0xffffffffu, h1[q], k);
                wacc[q][0]  += hk * w0.x; wacc[q][1]  += hk * w0.y;
                wacc[q][2]  += hk * w0.z; wacc[q][3]  += hk * w0.w;
                wacc[q][4]  += hk * w1.x; wacc[q][5]  += hk * w1.y;
                wacc[q][6]  += hk * w1.z; wacc[q][7]  += hk * w1.w;
                wacc[q][8]  += hk * w2.x; wacc[q][9]  += hk * w2.y;
                wacc[q][10] += hk * w2.z; wacc[q][11] += hk * w2.w;
            }
        }
        // ---- alpha = reduce_lane e*wacc, scaled ----
#pragma unroll
        for (int q = 0; q < 4; q++) {
            float my = 0.f;
#pragma unroll
            for (int d = 0; d < 12; d++) {
                float partial = e[q][d] * wacc[q][d];
#pragma unroll
                for (int o = 16; o > 0; o >>= 1)
                    partial += __shfl_xor_sync(0xffffffffu, partial, o);
                if (lane == d) my = partial * scale[q];
            }
            if (lane < 12) d_alpha[(size_t)(pb + q) * 12 + lane] = my;
        }
    }
}

// ---------------------------------------------------------------------------
// Per-atom-i aggregation. P rows prefetched into registers one pair ahead
// (idx_j read directly by every thread -> no smem dependency on the gather).
// ---------------------------------------------------------------------------
__global__ __launch_bounds__(128) void agg_kernel(
    const int*   __restrict__ idx_i, const int* __restrict__ idx_j,
    const float* __restrict__ sph,   const float* __restrict__ b_out,
    float* __restrict__ out)
{
    int atom = blockIdx.x;
    int c    = threadIdx.x;   // 0..127
    __shared__ int   srange[2];
    __shared__ float sal[2][12];
    __shared__ float ssph[2][16];

    if (c < 2) {
        int target = atom + c;
        int lo = 0, hi = NPAIR;
        while (lo < hi) {
            int mid = (lo + hi) >> 1;
            if (idx_i[mid] < target) lo = mid + 1; else hi = mid;
        }
        srange[c] = lo;
    }
    __syncthreads();
    int p0 = srange[0], p1 = srange[1];

    float acc[15];
#pragma unroll
    for (int m = 0; m < 15; m++) acc[m] = 0.f;

    float pv0 = 0.f, pv1 = 0.f, pv2 = 0.f, pv3 = 0.f;
    if (p0 < p1) {
        int j0 = idx_j[p0];
        const float* Pr = &d_P[(size_t)j0 * 512 + c];
        pv0 = Pr[0]; pv1 = Pr[128]; pv2 = Pr[256]; pv3 = Pr[384];
        if (c < 12)                 sal[0][c]     = d_alpha[(size_t)p0 * 12 + c];
        else if (c >= 32 && c < 47) ssph[0][c-32] = sph[(size_t)p0 * 15 + (c - 32)];
    }
    __syncthreads();

    for (int p = p0; p < p1; p++) {
        int b  = (p - p0) & 1;
        int nb = b ^ 1;
        // prefetch next pair: smem (alpha, sph) + register P row
        if (p + 1 < p1) {
            if (c < 12)                 sal[nb][c]     = d_alpha[(size_t)(p+1) * 12 + c];
            else if (c >= 32 && c < 47) ssph[nb][c-32] = sph[(size_t)(p+1) * 15 + (c - 32)];
        }
        int jn = (p + 1 < p1) ? idx_j[p + 1] : 0;
        const float* Pn = &d_P[(size_t)jn * 512 + c];
        float n0 = Pn[0], n1 = Pn[128], n2 = Pn[256], n3 = Pn[384];

        float e0 = sal[b][0]*pv0 + sal[b][1]*pv1 + sal[b][2] *pv2 + sal[b][3] *pv3;
        float e1 = sal[b][4]*pv0 + sal[b][5]*pv1 + sal[b][6] *pv2 + sal[b][7] *pv3;
        float e2 = sal[b][8]*pv0 + sal[b][9]*pv1 + sal[b][10]*pv2 + sal[b][11]*pv3;
        acc[0]  += ssph[b][0]  * e0;
        acc[1]  += ssph[b][1]  * e0;
        acc[2]  += ssph[b][2]  * e0;
        acc[3]  += ssph[b][3]  * e1;
        acc[4]  += ssph[b][4]  * e1;
        acc[5]  += ssph[b][5]  * e1;
        acc[6]  += ssph[b][6]  * e1;
        acc[7]  += ssph[b][7]  * e1;
        acc[8]  += ssph[b][8]  * e2;
        acc[9]  += ssph[b][9]  * e2;
        acc[10] += ssph[b][10] * e2;
        acc[11] += ssph[b][11] * e2;
        acc[12] += ssph[b][12] * e2;
        acc[13] += ssph[b][13] * e2;
        acc[14] += ssph[b][14] * e2;
        __syncthreads();
        pv0 = n0; pv1 = n1; pv2 = n2; pv3 = n3;
    }

    float bo = b_out[c];
#pragma unroll
    for (int m = 0; m < 15; m++)
        out[((size_t)atom * 15 + m) * 128 + c] = acc[m] + bo;
}

// ---------------------------------------------------------------------------
extern "C" void kernel_launch(void* const* d_in, const int* in_sizes, int n_in,
                              void* d_out, int out_size)
{
    const float* x     = (const float*)d_in[0];
    const float* rbf   = (const float*)d_in[1];
    const float* sph   = (const float*)d_in[2];
    const float* phi   = (const float*)d_in[3];
    const int*   idx_i = (const int*)  d_in[4];
    const int*   idx_j = (const int*)  d_in[5];
    const float* pmask = (const float*)d_in[6];
    const float* WQ    = (const float*)d_in[7];
    const float* WK    = (const float*)d_in[8];
    const float* W_in  = (const float*)d_in[9];
    const float* b_in  = (const float*)d_in[10];
    const float* Wf1   = (const float*)d_in[11];
    const float* bf1   = (const float*)d_in[12];
    const float* Wf2   = (const float*)d_in[13];
    const float* bf2   = (const float*)d_in[14];
    const float* W_out = (const float*)d_in[15];
    const float* b_out = (const float*)d_in[16];
    float* out = (float*)d_out;

    prep_kernel<<<(NATOMS + 31) / 32, 256>>>(x, W_in, b_in, WQ, WK, W_out);
    alpha_kernel<<<296, 256>>>(rbf, phi, pmask, idx_i, idx_j, Wf1, bf1, Wf2, bf2);
    agg_kernel<<<NATOMS, 128>>>(idx_i, idx_j, sph, b_out, out);
}